// round 5
// baseline (speedup 1.0000x reference)
#include <cuda_runtime.h>
#include <stdint.h>
#include <stddef.h>

#define T_TOK 4096
#define HDIM  1024
#define FDIM  2048
#define NEXP  8

// ---------------- scratch (__device__ globals: alloc-free) ----------------
__device__ int   g_cnt[NEXP];
__device__ int   g_tok[NEXP * T_TOK];
__device__ float g_wt [NEXP * T_TOK];
__device__ float g_h  [(size_t)NEXP * T_TOK * FDIM];   // silu(XW1)*XW3, tf32, k-perm
__device__ float g_xr [(size_t)T_TOK * HDIM];          // x tf32-rounded, k-perm
__device__ float g_w1t[(size_t)NEXP * FDIM * HDIM];    // w1^T [E][F][H], k-perm
__device__ float g_w3t[(size_t)NEXP * FDIM * HDIM];    // w3^T [E][F][H], k-perm
__device__ float g_w2t[(size_t)NEXP * HDIM * FDIM];    // w2^T [E][H][F], k-perm

// ---------------- helpers ----------------
__device__ __forceinline__ uint32_t smem_u32(const void* p) {
    uint32_t a;
    asm("{ .reg .u64 t; cvta.to.shared.u64 t, %1; cvt.u32.u64 %0, t; }" : "=r"(a) : "l"(p));
    return a;
}
__device__ __forceinline__ float rna_tf32(float f) {
    uint32_t r;
    asm("cvt.rna.tf32.f32 %0, %1;" : "=r"(r) : "f"(f));
    return __uint_as_float(r);
}
// logical k -> physical k within 16-blocks: phys = 4*(k%4) + k/4
__device__ __forceinline__ int perm16(int f) {
    return (f & ~15) | ((f & 3) << 2) | ((f >> 2) & 3);
}
// smem offset: row stride 128B (32 floats), 8 chunks of 16B, xor-swizzled
__device__ __forceinline__ uint32_t swoff(int row, int chunk) {
    return (uint32_t)(row * 128 + ((chunk ^ ((row & 1) << 2)) << 4));
}

#define CP_ASYNC16(dst, src) \
    asm volatile("cp.async.cg.shared.global [%0], [%1], 16;\n" :: "r"(dst), "l"(src))
#define CP_COMMIT() asm volatile("cp.async.commit_group;\n")
#define CP_WAIT0()  asm volatile("cp.async.wait_group 0;\n")
#define CP_WAIT1()  asm volatile("cp.async.wait_group 1;\n")

__device__ __forceinline__ void lds128(uint4& v, uint32_t addr) {
    asm volatile("ld.shared.v4.b32 {%0,%1,%2,%3}, [%4];"
                 : "=r"(v.x), "=r"(v.y), "=r"(v.z), "=r"(v.w) : "r"(addr));
}
__device__ __forceinline__ void mma8(float* d, uint32_t a0, uint32_t a1, uint32_t a2,
                                     uint32_t a3, uint32_t b0, uint32_t b1) {
    asm volatile(
        "mma.sync.aligned.m16n8k8.row.col.f32.tf32.tf32.f32 "
        "{%0,%1,%2,%3}, {%4,%5,%6,%7}, {%8,%9}, {%0,%1,%2,%3};\n"
        : "+f"(d[0]), "+f"(d[1]), "+f"(d[2]), "+f"(d[3])
        : "r"(a0), "r"(a1), "r"(a2), "r"(a3), "r"(b0), "r"(b1));
}

// ---------------- init ----------------
__global__ void init_counts() {
    if (threadIdx.x < NEXP) g_cnt[threadIdx.x] = 0;
}

// ---------------- router ----------------
__global__ void router_kernel(const float* __restrict__ x,
                              const float* __restrict__ gw,
                              float* __restrict__ logits_out,
                              int write_logits)
{
    int tok  = (blockIdx.x * blockDim.x + threadIdx.x) >> 5;
    int lane = threadIdx.x & 31;
    if (tok >= T_TOK) return;
    const float* xr = x + (size_t)tok * HDIM;

    float acc[NEXP];
#pragma unroll
    for (int e = 0; e < NEXP; e++) acc[e] = 0.f;
    for (int h = lane; h < HDIM; h += 32) {
        float xv = xr[h];
#pragma unroll
        for (int e = 0; e < NEXP; e++) acc[e] = fmaf(xv, gw[e * HDIM + h], acc[e]);
    }
#pragma unroll
    for (int e = 0; e < NEXP; e++) {
#pragma unroll
        for (int off = 16; off > 0; off >>= 1)
            acc[e] += __shfl_xor_sync(0xffffffffu, acc[e], off);
    }
    if (lane == 0) {
        if (write_logits) {
#pragma unroll
            for (int e = 0; e < NEXP; e++) logits_out[tok * NEXP + e] = acc[e];
        }
        float mx = acc[0];
#pragma unroll
        for (int e = 1; e < NEXP; e++) mx = fmaxf(mx, acc[e]);
        float p[NEXP], s = 0.f;
#pragma unroll
        for (int e = 0; e < NEXP; e++) { p[e] = __expf(acc[e] - mx); s += p[e]; }
        float inv = 1.f / s;
#pragma unroll
        for (int e = 0; e < NEXP; e++) p[e] *= inv;

        int i1 = 0; float m1 = p[0];
#pragma unroll
        for (int e = 1; e < NEXP; e++) if (p[e] > m1) { m1 = p[e]; i1 = e; }
        int i2 = -1; float m2 = -1.f;
#pragma unroll
        for (int e = 0; e < NEXP; e++) {
            if (e == i1) continue;
            if (p[e] > m2) { m2 = p[e]; i2 = e; }
        }
        int pos1 = atomicAdd(&g_cnt[i1], 1);
        g_tok[i1 * T_TOK + pos1] = tok;  g_wt[i1 * T_TOK + pos1] = m1;
        int pos2 = atomicAdd(&g_cnt[i2], 1);
        g_tok[i2 * T_TOK + pos2] = tok;  g_wt[i2 * T_TOK + pos2] = m2;
    }
}

// ---------------- pre-pass: round x to tf32 + k-permute (float4 out) ------
__global__ void round_x_perm(const float* __restrict__ in) {
    int p = (blockIdx.x * 256 + threadIdx.x) * 4;      // phys base
    int grp = p & ~15, j = (p >> 2) & 3;
    float4 o;
    o.x = rna_tf32(in[grp + j]);
    o.y = rna_tf32(in[grp + 4 + j]);
    o.z = rna_tf32(in[grp + 8 + j]);
    o.w = rna_tf32(in[grp + 12 + j]);
    *(float4*)(g_xr + p) = o;
}

// ---------------- pre-pass: round + transpose + k-perm weights (f4 both) --
// in: [E][K][N] -> out: [E][N][K] (K phys-permuted per 16), tf32-rounded
template<int W, int K, int N>
__global__ void round_transpose_kernel(const float* __restrict__ in) {
    __shared__ float t[32][33];
    float* out = (W == 0) ? g_w1t : (W == 1) ? g_w3t : g_w2t;
    const float* ie = in + (size_t)blockIdx.z * K * N;
    float* oe = out + (size_t)blockIdx.z * K * N;
    int n0 = blockIdx.x * 32, k0 = blockIdx.y * 32;

    int kr = threadIdx.x >> 3;            // 0..31
    int nc = (threadIdx.x & 7) * 4;
    float4 v = *(const float4*)(ie + (size_t)(k0 + kr) * N + n0 + nc);
    t[kr][nc] = v.x; t[kr][nc + 1] = v.y; t[kr][nc + 2] = v.z; t[kr][nc + 3] = v.w;
    __syncthreads();

    int nr = threadIdx.x >> 3;            // 0..31 (n within tile)
    int c  = threadIdx.x & 7;             // phys 16B chunk
    int g  = (c >> 2) * 16, j = c & 3;    // phys base = g + 4j, logical = g+4i+j
    float4 o;
    o.x = rna_tf32(t[g + j     ][nr]);
    o.y = rna_tf32(t[g + 4 + j ][nr]);
    o.z = rna_tf32(t[g + 8 + j ][nr]);
    o.w = rna_tf32(t[g + 12 + j][nr]);
    *(float4*)(oe + (size_t)(n0 + nr) * K + k0 + g + 4 * j) = o;
}

// =====================================================================
// GEMM13 fused: h = silu(Xg @ W1) * (Xg @ W3)
// BM=128, BN=64, BK=32, 128 thr (4 warps 2x2). Warp: 64 rows x 32 cols x 2 mats.
// smem/stage (32KB): A[0,16K) B1[16K,24K) B3[24K,32K). 3 stages.
// =====================================================================
__global__ void __launch_bounds__(128)
moe_gemm13()
{
    const int e   = blockIdx.z;
    const int cnt = g_cnt[e];
    const int m0  = blockIdx.x * 128;
    if (m0 >= cnt) return;
    const int n0  = blockIdx.y * 64;

    extern __shared__ char dsm[];
    const uint32_t sb = (smem_u32(dsm) + 127u) & ~127u;
    __shared__ const float* s_arow[128];

    const int tid  = threadIdx.x;
    const int warp = tid >> 5;
    const int lane = tid & 31;
    const int qr   = lane >> 2;
    const int qc   = lane & 3;
    const int rq   = warp & 1;       // M half
    const int cf   = warp >> 1;      // N half

    {
        int mm = min(m0 + tid, cnt - 1);
        s_arow[tid] = g_xr + (size_t)g_tok[e * T_TOK + mm] * HDIM;
    }
    __syncthreads();

    const float* b1b = g_w1t + (size_t)e * FDIM * HDIM + (size_t)n0 * HDIM;
    const float* b3b = g_w3t + (size_t)e * FDIM * HDIM + (size_t)n0 * HDIM;

    const int ch = tid & 7;
    const int rr = tid >> 3;         // 0..15
    const float* pA[8]; uint32_t dA[8];
#pragma unroll
    for (int i = 0; i < 8; i++) {
        int row = i * 16 + rr;
        pA[i] = s_arow[row] + ch * 4;
        dA[i] = sb + swoff(row, ch);
    }
    const float* pB1[4]; const float* pB3[4]; uint32_t dB[4];
#pragma unroll
    for (int i = 0; i < 4; i++) {
        int row = i * 16 + rr;       // 0..63
        pB1[i] = b1b + (size_t)row * HDIM + ch * 4;
        pB3[i] = b3b + (size_t)row * HDIM + ch * 4;
        dB[i]  = sb + 16384u + swoff(row, ch);
    }

#define LOAD13(st_, k0_) do {                                             \
    uint32_t so_ = (uint32_t)(st_) * 32768u;                              \
    _Pragma("unroll")                                                     \
    for (int i_ = 0; i_ < 8; i_++)                                        \
        CP_ASYNC16(dA[i_] + so_, pA[i_] + (k0_));                         \
    _Pragma("unroll")                                                     \
    for (int i_ = 0; i_ < 4; i_++) {                                      \
        CP_ASYNC16(dB[i_] + so_,         pB1[i_] + (k0_));                \
        CP_ASYNC16(dB[i_] + 8192u + so_, pB3[i_] + (k0_));                \
    }                                                                     \
    CP_COMMIT();                                                          \
} while (0)

    float acc1[4][4][4], acc3[4][4][4];
#pragma unroll
    for (int mt = 0; mt < 4; mt++)
#pragma unroll
        for (int nt = 0; nt < 4; nt++)
#pragma unroll
            for (int i = 0; i < 4; i++) { acc1[mt][nt][i] = 0.f; acc3[mt][nt][i] = 0.f; }

    LOAD13(0, 0);
    LOAD13(1, 32);
    const int NT = HDIM / 32;   // 32
    for (int t = 0; t < NT; t++) {
        const uint32_t st = (uint32_t)(t % 3) * 32768u;
        if (t == NT - 1) CP_WAIT0(); else CP_WAIT1();
        __syncthreads();
        if (t + 2 < NT) LOAD13((t + 2) % 3, (t + 2) * 32);

#pragma unroll
        for (int s = 0; s < 2; s++) {
            uint4 alo[4], ahi[4];
#pragma unroll
            for (int mt = 0; mt < 4; mt++) {
                int r = rq * 64 + mt * 16 + qr;
                lds128(alo[mt], sb + st + swoff(r,     4 * s + qc));
                lds128(ahi[mt], sb + st + swoff(r + 8, 4 * s + qc));
            }
#pragma unroll
            for (int nt = 0; nt < 4; nt++) {
                int n = cf * 32 + nt * 8 + qr;
                uint4 b1v, b3v;
                lds128(b1v, sb + st + 16384u + swoff(n, 4 * s + qc));
                lds128(b3v, sb + st + 24576u + swoff(n, 4 * s + qc));
#pragma unroll
                for (int mt = 0; mt < 4; mt++) {
                    mma8(acc1[mt][nt], alo[mt].x, ahi[mt].x, alo[mt].y, ahi[mt].y, b1v.x, b1v.y);
                    mma8(acc1[mt][nt], alo[mt].z, ahi[mt].z, alo[mt].w, ahi[mt].w, b1v.z, b1v.w);
                    mma8(acc3[mt][nt], alo[mt].x, ahi[mt].x, alo[mt].y, ahi[mt].y, b3v.x, b3v.y);
                    mma8(acc3[mt][nt], alo[mt].z, ahi[mt].z, alo[mt].w, ahi[mt].w, b3v.z, b3v.w);
                }
            }
        }
    }

    // epilogue: g_h[m][perm16(f)] = rna(silu(d1)*d3)
#pragma unroll
    for (int mt = 0; mt < 4; mt++) {
#pragma unroll
        for (int h = 0; h < 2; h++) {
            int m = m0 + rq * 64 + mt * 16 + qr + 8 * h;
            if (m >= cnt) continue;
            float* hrow = g_h + ((size_t)e * T_TOK + m) * FDIM;
#pragma unroll
            for (int nt = 0; nt < 4; nt++) {
#pragma unroll
                for (int b = 0; b < 2; b++) {
                    float d1 = acc1[mt][nt][2 * h + b];
                    float d3 = acc3[mt][nt][2 * h + b];
                    float v = rna_tf32(d1 / (1.f + __expf(-d1)) * d3);
                    int f = n0 + cf * 32 + nt * 8 + qc * 2 + b;
                    hrow[perm16(f)] = v;
                }
            }
        }
    }
#undef LOAD13
}

// =====================================================================
// GEMM2: y += wt * (h @ W2).  BM=128, BN=128, BK=32, 128 thr (2x2 warps).
// Warp: 64 rows x 64 cols. smem/stage (32KB): A[0,16K) B[16K,32K). 3 stages.
// =====================================================================
__global__ void __launch_bounds__(128)
moe_gemm2(float* __restrict__ y)
{
    const int e   = blockIdx.z;
    const int cnt = g_cnt[e];
    const int m0  = blockIdx.x * 128;
    if (m0 >= cnt) return;
    const int n0  = blockIdx.y * 128;

    extern __shared__ char dsm[];
    const uint32_t sb = (smem_u32(dsm) + 127u) & ~127u;
    __shared__ const float* s_arow[128];

    const int tid  = threadIdx.x;
    const int warp = tid >> 5;
    const int lane = tid & 31;
    const int qr   = lane >> 2;
    const int qc   = lane & 3;
    const int rq   = warp & 1;
    const int cf   = warp >> 1;

    {
        int mm = min(m0 + tid, cnt - 1);
        s_arow[tid] = g_h + ((size_t)e * T_TOK + mm) * FDIM;
    }
    __syncthreads();

    const float* bb = g_w2t + (size_t)e * HDIM * FDIM + (size_t)n0 * FDIM;

    const int ch = tid & 7;
    const int rr = tid >> 3;
    const float* pA[8]; uint32_t dA[8]; const float* pB[8]; uint32_t dB[8];
#pragma unroll
    for (int i = 0; i < 8; i++) {
        int row = i * 16 + rr;
        pA[i] = s_arow[row] + ch * 4;
        dA[i] = sb + swoff(row, ch);
        pB[i] = bb + (size_t)row * FDIM + ch * 4;
        dB[i] = sb + 16384u + swoff(row, ch);
    }

#define LOAD2(st_, k0_) do {                                              \
    uint32_t so_ = (uint32_t)(st_) * 32768u;                              \
    _Pragma("unroll")                                                     \
    for (int i_ = 0; i_ < 8; i_++) {                                      \
        CP_ASYNC16(dA[i_] + so_, pA[i_] + (k0_));                         \
        CP_ASYNC16(dB[i_] + so_, pB[i_] + (k0_));                         \
    }                                                                     \
    CP_COMMIT();                                                          \
} while (0)

    float acc[4][8][4];
#pragma unroll
    for (int mt = 0; mt < 4; mt++)
#pragma unroll
        for (int nt = 0; nt < 8; nt++)
#pragma unroll
            for (int i = 0; i < 4; i++) acc[mt][nt][i] = 0.f;

    LOAD2(0, 0);
    LOAD2(1, 32);
    const int NT = FDIM / 32;   // 64
    for (int t = 0; t < NT; t++) {
        const uint32_t st = (uint32_t)(t % 3) * 32768u;
        if (t == NT - 1) CP_WAIT0(); else CP_WAIT1();
        __syncthreads();
        if (t + 2 < NT) LOAD2((t + 2) % 3, (t + 2) * 32);

#pragma unroll
        for (int s = 0; s < 2; s++) {
            uint4 alo[4], ahi[4];
#pragma unroll
            for (int mt = 0; mt < 4; mt++) {
                int r = rq * 64 + mt * 16 + qr;
                lds128(alo[mt], sb + st + swoff(r,     4 * s + qc));
                lds128(ahi[mt], sb + st + swoff(r + 8, 4 * s + qc));
            }
#pragma unroll
            for (int nt = 0; nt < 8; nt++) {
                int n = cf * 64 + nt * 8 + qr;
                uint4 bv;
                lds128(bv, sb + st + 16384u + swoff(n, 4 * s + qc));
#pragma unroll
                for (int mt = 0; mt < 4; mt++) {
                    mma8(acc[mt][nt], alo[mt].x, ahi[mt].x, alo[mt].y, ahi[mt].y, bv.x, bv.y);
                    mma8(acc[mt][nt], alo[mt].z, ahi[mt].z, alo[mt].w, ahi[mt].w, bv.z, bv.w);
                }
            }
        }
    }

    // epilogue: y[tok] += wt * D (atomic combine)
#pragma unroll
    for (int mt = 0; mt < 4; mt++) {
#pragma unroll
        for (int h = 0; h < 2; h++) {
            int m = m0 + rq * 64 + mt * 16 + qr + 8 * h;
            if (m >= cnt) continue;
            float w   = g_wt [e * T_TOK + m];
            int   tok = g_tok[e * T_TOK + m];
            float* yrow = y + (size_t)tok * HDIM + n0 + cf * 64;
#pragma unroll
            for (int nt = 0; nt < 8; nt++) {
#pragma unroll
                for (int b = 0; b < 2; b++)
                    atomicAdd(yrow + nt * 8 + qc * 2 + b, w * acc[mt][nt][2 * h + b]);
            }
        }
    }
#undef LOAD2
}

// ---------------- launch ----------------
extern "C" void kernel_launch(void* const* d_in, const int* in_sizes, int n_in,
                              void* d_out, int out_size)
{
    const float* x  = (const float*)d_in[0];   // [2,2048,1024]
    const float* gw = (const float*)d_in[1];   // [8,1024]
    const float* w1 = (const float*)d_in[2];   // [8,1024,2048]
    const float* w3 = (const float*)d_in[3];   // [8,1024,2048]
    const float* w2 = (const float*)d_in[4];   // [8,2048,1024]
    float* out = (float*)d_out;

    const int SMEM = 3 * 32768 + 128;   // 98432
    cudaFuncSetAttribute(moe_gemm13, cudaFuncAttributeMaxDynamicSharedMemorySize, SMEM);
    cudaFuncSetAttribute(moe_gemm2,  cudaFuncAttributeMaxDynamicSharedMemorySize, SMEM);

    cudaMemsetAsync(out, 0, (size_t)T_TOK * HDIM * sizeof(float));
    init_counts<<<1, 32>>>();

    int write_logits = (out_size >= T_TOK * HDIM + T_TOK * NEXP) ? 1 : 0;
    router_kernel<<<T_TOK / 4, 128>>>(x, gw, out + (size_t)T_TOK * HDIM, write_logits);

    round_x_perm<<<T_TOK * HDIM / 1024, 256>>>(x);
    {
        dim3 b(256);
        round_transpose_kernel<0, HDIM, FDIM><<<dim3(FDIM / 32, HDIM / 32, NEXP), b>>>(w1);
        round_transpose_kernel<1, HDIM, FDIM><<<dim3(FDIM / 32, HDIM / 32, NEXP), b>>>(w3);
        round_transpose_kernel<2, FDIM, HDIM><<<dim3(HDIM / 32, FDIM / 32, NEXP), b>>>(w2);
    }

    // grid.x = M-blocks fastest (B-tile / expert A-slice L2 reuse)
    moe_gemm13<<<dim3(T_TOK / 128, FDIM / 64, NEXP), 128, SMEM>>>();
    moe_gemm2 <<<dim3(T_TOK / 128, HDIM / 128, NEXP), 128, SMEM>>>(out);
}